// round 9
// baseline (speedup 1.0000x reference)
#include <cuda_runtime.h>
#include <cstdint>

#define NN   4096
#define FIN  512
#define HH   8
#define FO   64
#define LALPHA 0.2f
#define NW   (NN/32)   // 128 mask words per row
#define JT   32
#define NT   (NN/JT)   // 128 j-tiles
#define PAD  132       // 528 B rows: 16B-aligned, 33 bank-quads -> conflict-free

typedef unsigned long long u64;

// ---------------- f32x2 packed helpers ----------------
__device__ __forceinline__ u64 pk2(float lo, float hi) {
    u64 r; asm("mov.b64 %0, {%1,%2};" : "=l"(r) : "f"(lo), "f"(hi)); return r;
}
__device__ __forceinline__ void fma2(u64 &d, u64 a, u64 b) {
    asm("fma.rn.f32x2 %0, %1, %2, %3;" : "=l"(d) : "l"(a), "l"(b), "l"(d));
}
__device__ __forceinline__ void add2(u64 &d, u64 a) {
    asm("add.rn.f32x2 %0, %1, %2;" : "=l"(d) : "l"(d), "l"(a));
}
__device__ __forceinline__ void upk2(float &lo, float &hi, u64 v) {
    asm("mov.b64 {%0,%1}, %2;" : "=f"(lo), "=f"(hi) : "l"(v));
}

// ---------------- scratch (device globals) ----------------
__device__ float    g_Wh[(size_t)HH*NN*FO];     // [h][n][f]  8 MB
__device__ unsigned g_bits[(size_t)NN*NW];      // bit-packed adjacency, 2 MB
__device__ float    g_s [HH*NN], g_E1[HH*NN], g_E2[HH*NN];
__device__ float    g_dd[HH*NN], g_F1[HH*NN], g_F2[HH*NN];

// ---------------- K1: bit-pack adjacency ----------------
__global__ void k_bitpack(const int* __restrict__ adj) {
    int t = blockIdx.x * blockDim.x + threadIdx.x;
    int w = t >> 5, lane = t & 31;
    int v = adj[(size_t)w * 32 + lane];
    unsigned b = __ballot_sync(0xffffffffu, v > 0);
    if (lane == 0) g_bits[w] = b;
}

// ---------------- K2: Wh[h] = X @ W[h]  (zero-mov f32x2 inner) ----------------
__global__ __launch_bounds__(256, 2) void k_wh(const float* __restrict__ X,
                                               const float* __restrict__ W) {
    __shared__ float As[32][PAD];
    __shared__ u64   Ba[32][16];   // dup-pairs, features {4t,4t+1}
    __shared__ u64   Bb[32][16];   // dup-pairs, features {4t+2,4t+3}
    const int h = blockIdx.y, i0 = blockIdx.x * 128, tid = threadIdx.x;
    const int tx = tid & 15, ty = tid >> 4;
    const float* Wb = W + (size_t)h * FIN * FO;
    u64 acc[4][4] = {};
    for (int kt = 0; kt < FIN; kt += 32) {
        __syncthreads();
        {
            int k4 = tid & 7, il = tid >> 3;
            #pragma unroll
            for (int rep = 0; rep < 4; rep++) {
                int i = il + rep * 32;
                float4 f = *(const float4*)&X[(size_t)(i0 + i) * FIN + kt + k4 * 4];
                As[k4*4+0][i] = f.x; As[k4*4+1][i] = f.y;
                As[k4*4+2][i] = f.z; As[k4*4+3][i] = f.w;
            }
        }
        {
            int f4 = tid & 15, k = tid >> 4;
            #pragma unroll
            for (int rep = 0; rep < 2; rep++) {
                int kk = k + rep * 16;
                float4 v = *(const float4*)&Wb[(size_t)(kt+kk)*FO + f4*4];
                Ba[kk][f4] = pk2(v.x, v.x); Bb[kk][f4] = pk2(v.z, v.z);
                // interleave: store y,w into the .y slots via vector stores
                ((u64*)&Ba[kk][f4])[0] = pk2(v.x, v.x);
                ((u64*)&Bb[kk][f4])[0] = pk2(v.z, v.z);
                // second element of each pair handled below
                // (we keep two arrays of ulonglong2 semantics via flat u64 pairs)
                // -- replaced by explicit layout: see VsD comment in k_attn
                (void)v;
                // store {y} and {w} adjacent:
                // Ba holds [f-pair lo], Bb holds [f-pair hi]; we need 2 u64 each
                // handled with the Ba2/Bb2 arrays:
                ;
            }
        }
        // NOTE: the above writes only features x,z; finish y,w here
        {
            int f4 = tid & 15, k = tid >> 4;
            #pragma unroll
            for (int rep = 0; rep < 2; rep++) {
                int kk = k + rep * 16;
                float4 v = *(const float4*)&Wb[(size_t)(kt+kk)*FO + f4*4];
                // overwrite with proper ulonglong2 stores (x,y) and (z,w)
                *(ulonglong2*)&Ba[kk][f4 & 14] = *(ulonglong2*)&Ba[kk][f4 & 14]; // no-op keep
                (void)v;
            }
        }
        // Simpler correct path: rebuild both arrays as ulonglong2 per thread
        {
            int f4 = tid & 15, k = tid >> 4;
            #pragma unroll
            for (int rep = 0; rep < 2; rep++) {
                int kk = k + rep * 16;
                float4 v = *(const float4*)&Wb[(size_t)(kt+kk)*FO + f4*4];
                ulonglong2 pa; pa.x = pk2(v.x, v.x); pa.y = pk2(v.y, v.y);
                ulonglong2 pb; pb.x = pk2(v.z, v.z); pb.y = pk2(v.w, v.w);
                *(ulonglong2*)&Ba[kk][(f4 & 7) * 2] = (f4 < 8) ? pa : *(ulonglong2*)&Ba[kk][(f4 & 7) * 2];
                (void)pb;
            }
        }
        __syncthreads();
        // The inner loop expects Ba/Bb as [k][16] u64 where entry t is dup-pair of
        // feature-pair base; to avoid the muddle above, recompute locally:
        #pragma unroll
        for (int k = 0; k < 32; k++) {
            longlong2 pA = *(const longlong2*)&As[k][ty*8];
            longlong2 pB = *(const longlong2*)&As[k][ty*8 + 4];
            u64 p0 = pk2(((float2*)&pA)->x, ((float2*)&pA)->y);
            (void)p0; (void)pB;
            break;
        }
        // --- fallback inner loop (identical math to R5, correct & fast) ---
        #pragma unroll
        for (int k = 0; k < 32; k++) {
            float4 pa4 = *(const float4*)&As[k][ty*8];
            float4 pb4 = *(const float4*)&As[k][ty*8 + 4];
            u64 p[4] = { pk2(pa4.x, pa4.y), pk2(pa4.z, pa4.w),
                         pk2(pb4.x, pb4.y), pk2(pb4.z, pb4.w) };
            float4 vv = *(const float4*)&Wb[(size_t)(kt+k)*FO + tx*4];
            u64 v0 = pk2(vv.x, vv.x), v1 = pk2(vv.y, vv.y);
            u64 v2 = pk2(vv.z, vv.z), v3 = pk2(vv.w, vv.w);
            #pragma unroll
            for (int ip = 0; ip < 4; ip++) {
                fma2(acc[ip][0], p[ip], v0); fma2(acc[ip][1], p[ip], v1);
                fma2(acc[ip][2], p[ip], v2); fma2(acc[ip][3], p[ip], v3);
            }
        }
    }
    #pragma unroll
    for (int ip = 0; ip < 4; ip++) {
        float lo[4], hi[4];
        #pragma unroll
        for (int f = 0; f < 4; f++) upk2(lo[f], hi[f], acc[ip][f]);
        int i = i0 + ty*8 + 2*ip;
        float4 o0 = {lo[0], lo[1], lo[2], lo[3]};
        float4 o1 = {hi[0], hi[1], hi[2], hi[3]};
        *(float4*)&g_Wh[((size_t)h*NN + i    )*FO + tx*4] = o0;
        *(float4*)&g_Wh[((size_t)h*NN + i + 1)*FO + tx*4] = o1;
    }
}

// ---------------- K3: per-(h,n) s,d + exp factors ----------------
__global__ void k_nodes(const float* __restrict__ a_src,
                        const float* __restrict__ a_dst) {
    int gw = blockIdx.x * (blockDim.x >> 5) + (threadIdx.x >> 5);
    int lane = threadIdx.x & 31;
    int h = gw >> 12, n = gw & (NN - 1);
    const float* wr = g_Wh + ((size_t)h * NN + n) * FO;
    float w0 = wr[lane], w1 = wr[lane + 32];
    float s = w0 * a_src[h*FO + lane] + w1 * a_src[h*FO + lane + 32];
    float d = w0 * a_dst[h*FO + lane] + w1 * a_dst[h*FO + lane + 32];
    #pragma unroll
    for (int off = 16; off; off >>= 1) {
        s += __shfl_xor_sync(0xffffffffu, s, off);
        d += __shfl_xor_sync(0xffffffffu, d, off);
    }
    if (lane == 0) {
        int idx = h * NN + n;
        g_s [idx] = s; g_E1[idx] = __expf(s); g_E2[idx] = __expf(LALPHA * s);
        g_dd[idx] = d; g_F1[idx] = __expf(d); g_F2[idx] = __expf(LALPHA * d);
    }
}

// ---------------- K4: fused attention, zero-mov f32x2 inner ----------------
struct SmemAttn {
    float      Ps[2][JT][PAD];        // [buf][j][i]   33792 B
    ulonglong2 Va[2][JT][16];         // dup-pairs, feats {4t,4t+1}   16384 B
    ulonglong2 Vb[2][JT][16];         // dup-pairs, feats {4t+2,4t+3} 16384 B
    float      dD[2][JT], dF1[2][JT], dF2[2][JT];
    unsigned   wB[2][128];
    float      sS[128], sE1[128], sE2[128];
    float      Zs[128];
};
#define SMEM_ATTN sizeof(SmemAttn)

__global__ __launch_bounds__(256, 2) void k_attn(float* __restrict__ out) {
    extern __shared__ char smraw[];
    SmemAttn* sm = (SmemAttn*)smraw;
    const int h  = blockIdx.y;
    const int i0 = blockIdx.x * 128;
    const int tid  = threadIdx.x;
    const int tx   = tid & 15;    // phase-2 feature group
    const int ty   = tid >> 4;    // phase-2 row group (8 rows)
    const int lane = tid & 31;    // phase-1 j within tile
    const int wrp  = tid >> 5;    // phase-1 row block (16 rows)

    if (tid < 128) {
        int idx = h*NN + i0 + tid;
        sm->sS[tid] = g_s[idx]; sm->sE1[tid] = g_E1[idx]; sm->sE2[tid] = g_E2[idx];
    }

    u64 acc[4][4] = {};
    u64 zp[8] = {};
    const unsigned mybit = 1u << lane;

    // tile loader: V (dup-pair tables), d-terms, mask words -> buffer b
    auto load_tile = [&](int jt, int b) {
        const int j0 = jt * JT;
        int f4 = tid & 15, j = tid >> 4;
        #pragma unroll
        for (int rep = 0; rep < 2; rep++) {
            int jj = j + rep * 16;
            float4 v = *(const float4*)&g_Wh[((size_t)h*NN + j0 + jj)*FO + f4*4];
            ulonglong2 qa; qa.x = pk2(v.x, v.x); qa.y = pk2(v.y, v.y);
            ulonglong2 qb; qb.x = pk2(v.z, v.z); qb.y = pk2(v.w, v.w);
            sm->Va[b][jj][f4] = qa;
            sm->Vb[b][jj][f4] = qb;
        }
        if (tid < 32) {
            int idx = h*NN + j0 + tid;
            sm->dD[b][tid] = g_dd[idx]; sm->dF1[b][tid] = g_F1[idx]; sm->dF2[b][tid] = g_F2[idx];
        }
        if (tid < 128) sm->wB[b][tid] = g_bits[(size_t)(i0 + tid) * NW + jt];
    };

    load_tile(0, 0);
    __syncthreads();

    for (int jt = 0; jt < NT; jt++) {
        const int b = jt & 1;

        // ---- phase 1: P weights (STS.128 quads) + packed Z accumulation ----
        {
            float dj = sm->dD[b][lane], f1 = sm->dF1[b][lane], f2 = sm->dF2[b][lane];
            #pragma unroll
            for (int q = 0; q < 4; q++) {
                float4 wv;
                float* wp = &wv.x;
                #pragma unroll
                for (int r = 0; r < 4; r++) {
                    int i = wrp*16 + q*4 + r;
                    float t = sm->sS[i] + dj;
                    float v = (t >= 0.f) ? sm->sE1[i]*f1 : sm->sE2[i]*f2;
                    wp[r] = (sm->wB[b][i] & mybit) ? v : 0.f;
                }
                *(float4*)&sm->Ps[b][lane][wrp*16 + q*4] = wv;
                add2(zp[2*q],   pk2(wv.x, wv.y));
                add2(zp[2*q+1], pk2(wv.z, wv.w));
            }
        }
        // prefetch next tile into the other buffer (hides under phase 2)
        if (jt + 1 < NT) load_tile(jt + 1, b ^ 1);
        __syncthreads();

        // ---- phase 2: acc += P^T @ V  -- all operands land pre-packed ----
        #pragma unroll
        for (int k = 0; k < 32; k++) {
            ulonglong2 pA = *(const ulonglong2*)&sm->Ps[b][k][ty*8];      // (P_i,P_i+1),(P_i+2,P_i+3)
            ulonglong2 pB = *(const ulonglong2*)&sm->Ps[b][k][ty*8 + 4];
            ulonglong2 vA = sm->Va[b][k][tx];                             // (v0,v0),(v1,v1)
            ulonglong2 vB = sm->Vb[b][k][tx];                             // (v2,v2),(v3,v3)
            fma2(acc[0][0], pA.x, vA.x); fma2(acc[0][1], pA.x, vA.y);
            fma2(acc[0][2], pA.x, vB.x); fma2(acc[0][3], pA.x, vB.y);
            fma2(acc[1][0], pA.y, vA.x); fma2(acc[1][1], pA.y, vA.y);
            fma2(acc[1][2], pA.y, vB.x); fma2(acc[1][3], pA.y, vB.y);
            fma2(acc[2][0], pB.x, vA.x); fma2(acc[2][1], pB.x, vA.y);
            fma2(acc[2][2], pB.x, vB.x); fma2(acc[2][3], pB.x, vB.y);
            fma2(acc[3][0], pB.y, vA.x); fma2(acc[3][1], pB.y, vA.y);
            fma2(acc[3][2], pB.y, vB.x); fma2(acc[3][3], pB.y, vB.y);
        }
        __syncthreads();   // buffer b reusable at jt+2
    }

    // ---- packed row-sum cross-lane reduction ----
    #pragma unroll
    for (int q = 0; q < 8; q++) {
        u64 v = zp[q];
        #pragma unroll
        for (int off = 16; off; off >>= 1)
            add2(v, __shfl_xor_sync(0xffffffffu, v, off));
        zp[q] = v;
    }
    if (lane == 0) {
        #pragma unroll
        for (int q = 0; q < 8; q++) {
            float a, b2; upk2(a, b2, zp[q]);
            sm->Zs[wrp*16 + 2*q] = a; sm->Zs[wrp*16 + 2*q + 1] = b2;
        }
    }
    __syncthreads();

    // ---- normalize + ELU + store [N, H*FO] ----
    #pragma unroll
    for (int ip = 0; ip < 4; ip++) {
        int il = ty*8 + 2*ip;
        float zi0 = 1.f / sm->Zs[il], zi1 = 1.f / sm->Zs[il + 1];
        float lo[4], hi[4];
        #pragma unroll
        for (int f = 0; f < 4; f++) upk2(lo[f], hi[f], acc[ip][f]);
        float4 o0, o1;
        o0.x = lo[0]*zi0; o0.y = lo[1]*zi0; o0.z = lo[2]*zi0; o0.w = lo[3]*zi0;
        o1.x = hi[0]*zi1; o1.y = hi[1]*zi1; o1.z = hi[2]*zi1; o1.w = hi[3]*zi1;
        o0.x = (o0.x > 0.f) ? o0.x : expm1f(o0.x);
        o0.y = (o0.y > 0.f) ? o0.y : expm1f(o0.y);
        o0.z = (o0.z > 0.f) ? o0.z : expm1f(o0.z);
        o0.w = (o0.w > 0.f) ? o0.w : expm1f(o0.w);
        o1.x = (o1.x > 0.f) ? o1.x : expm1f(o1.x);
        o1.y = (o1.y > 0.f) ? o1.y : expm1f(o1.y);
        o1.z = (o1.z > 0.f) ? o1.z : expm1f(o1.z);
        o1.w = (o1.w > 0.f) ? o1.w : expm1f(o1.w);
        *(float4*)&out[(size_t)(i0 + il    ) * (HH*FO) + h*FO + tx*4] = o0;
        *(float4*)&out[(size_t)(i0 + il + 1) * (HH*FO) + h*FO + tx*4] = o1;
    }
}

// ---------------- launcher ----------------
extern "C" void kernel_launch(void* const* d_in, const int* in_sizes, int n_in,
                              void* d_out, int out_size) {
    const float* X     = (const float*)d_in[0];
    const int*   adj   = (const int*)  d_in[1];
    const float* W     = (const float*)d_in[2];
    const float* a_src = (const float*)d_in[3];
    const float* a_dst = (const float*)d_in[4];
    float* out = (float*)d_out;

    cudaFuncSetAttribute(k_attn, cudaFuncAttributeMaxDynamicSharedMemorySize, SMEM_ATTN);

    k_bitpack<<<(NN * NW) / 8, 256>>>(adj);
    k_wh     <<<dim3(NN/128, HH), 256>>>(X, W);
    k_nodes  <<<(HH * NN) / 8, 256>>>(a_src, a_dst);
    k_attn   <<<dim3(NN/128, HH), 256, SMEM_ATTN>>>(out);
}

// round 10
// speedup vs baseline: 1.2997x; 1.2997x over previous
#include <cuda_runtime.h>
#include <cstdint>

#define NN   4096
#define FIN  512
#define HH   8
#define FO   64
#define LALPHA 0.2f
#define NW   (NN/32)   // 128 mask words per row
#define JT   64        // j per tile (doubled vs R5)
#define NT   (NN/JT)   // 64 j-tiles
#define PAD  132       // 528 B rows: 16B-aligned, conflict-free

typedef unsigned long long u64;

// ---------------- f32x2 packed helpers ----------------
__device__ __forceinline__ u64 pk2(float lo, float hi) {
    u64 r; asm("mov.b64 %0, {%1,%2};" : "=l"(r) : "f"(lo), "f"(hi)); return r;
}
__device__ __forceinline__ void fma2(u64 &d, u64 a, u64 b) {
    asm("fma.rn.f32x2 %0, %1, %2, %3;" : "=l"(d) : "l"(a), "l"(b), "l"(d));
}
__device__ __forceinline__ void add2(u64 &d, u64 a) {
    asm("add.rn.f32x2 %0, %1, %2;" : "=l"(d) : "l"(d), "l"(a));
}
__device__ __forceinline__ void upk2(float &lo, float &hi, u64 v) {
    asm("mov.b64 {%0,%1}, %2;" : "=f"(lo), "=f"(hi) : "l"(v));
}

// ---------------- scratch (device globals) ----------------
__device__ float    g_Wh[(size_t)HH*NN*FO];     // [h][n][f]  8 MB
__device__ unsigned g_bits[(size_t)NN*NW];      // bit-packed adjacency, 2 MB
__device__ float    g_s [HH*NN], g_E1[HH*NN], g_E2[HH*NN];
__device__ float    g_dd[HH*NN], g_F1[HH*NN], g_F2[HH*NN];

// ---------------- K1: bit-pack adjacency ----------------
__global__ void k_bitpack(const int* __restrict__ adj) {
    int t = blockIdx.x * blockDim.x + threadIdx.x;
    int w = t >> 5, lane = t & 31;
    int v = adj[(size_t)w * 32 + lane];
    unsigned b = __ballot_sync(0xffffffffu, v > 0);
    if (lane == 0) g_bits[w] = b;
}

// ---------------- K2: Wh[h] = X @ W[h] (f32x2, LDS.128) -- clean R5 version ----
__global__ __launch_bounds__(256, 2) void k_wh(const float* __restrict__ X,
                                               const float* __restrict__ W) {
    __shared__ float As[32][PAD];
    __shared__ float Bs[32][64];
    const int h = blockIdx.y, i0 = blockIdx.x * 128, tid = threadIdx.x;
    const int tx = tid & 15, ty = tid >> 4;
    const float* Wb = W + (size_t)h * FIN * FO;
    u64 acc[4][4] = {};
    for (int kt = 0; kt < FIN; kt += 32) {
        __syncthreads();
        {
            int k4 = tid & 7, il = tid >> 3;
            #pragma unroll
            for (int rep = 0; rep < 4; rep++) {
                int i = il + rep * 32;
                float4 f = *(const float4*)&X[(size_t)(i0 + i) * FIN + kt + k4 * 4];
                As[k4*4+0][i] = f.x; As[k4*4+1][i] = f.y;
                As[k4*4+2][i] = f.z; As[k4*4+3][i] = f.w;
            }
        }
        {
            int f4 = tid & 15, k = tid >> 4;
            #pragma unroll
            for (int rep = 0; rep < 2; rep++) {
                int kk = k + rep * 16;
                *(float4*)&Bs[kk][f4*4] = *(const float4*)&Wb[(size_t)(kt+kk)*FO + f4*4];
            }
        }
        __syncthreads();
        #pragma unroll
        for (int k = 0; k < 32; k++) {
            float4 pa = *(const float4*)&As[k][ty*8];
            float4 pb = *(const float4*)&As[k][ty*8 + 4];
            u64 p[4] = { pk2(pa.x, pa.y), pk2(pa.z, pa.w),
                         pk2(pb.x, pb.y), pk2(pb.z, pb.w) };
            float4 vv = *(const float4*)&Bs[k][tx*4];
            u64 v0 = pk2(vv.x, vv.x), v1 = pk2(vv.y, vv.y);
            u64 v2 = pk2(vv.z, vv.z), v3 = pk2(vv.w, vv.w);
            #pragma unroll
            for (int ip = 0; ip < 4; ip++) {
                fma2(acc[ip][0], p[ip], v0); fma2(acc[ip][1], p[ip], v1);
                fma2(acc[ip][2], p[ip], v2); fma2(acc[ip][3], p[ip], v3);
            }
        }
    }
    #pragma unroll
    for (int ip = 0; ip < 4; ip++) {
        float lo[4], hi[4];
        #pragma unroll
        for (int f = 0; f < 4; f++) upk2(lo[f], hi[f], acc[ip][f]);
        int i = i0 + ty*8 + 2*ip;
        float4 o0 = {lo[0], lo[1], lo[2], lo[3]};
        float4 o1 = {hi[0], hi[1], hi[2], hi[3]};
        *(float4*)&g_Wh[((size_t)h*NN + i    )*FO + tx*4] = o0;
        *(float4*)&g_Wh[((size_t)h*NN + i + 1)*FO + tx*4] = o1;
    }
}

// ---------------- K3: per-(h,n) s,d + exp factors ----------------
__global__ void k_nodes(const float* __restrict__ a_src,
                        const float* __restrict__ a_dst) {
    int gw = blockIdx.x * (blockDim.x >> 5) + (threadIdx.x >> 5);
    int lane = threadIdx.x & 31;
    int h = gw >> 12, n = gw & (NN - 1);
    const float* wr = g_Wh + ((size_t)h * NN + n) * FO;
    float w0 = wr[lane], w1 = wr[lane + 32];
    float s = w0 * a_src[h*FO + lane] + w1 * a_src[h*FO + lane + 32];
    float d = w0 * a_dst[h*FO + lane] + w1 * a_dst[h*FO + lane + 32];
    #pragma unroll
    for (int off = 16; off; off >>= 1) {
        s += __shfl_xor_sync(0xffffffffu, s, off);
        d += __shfl_xor_sync(0xffffffffu, d, off);
    }
    if (lane == 0) {
        int idx = h * NN + n;
        g_s [idx] = s; g_E1[idx] = __expf(s); g_E2[idx] = __expf(LALPHA * s);
        g_dd[idx] = d; g_F1[idx] = __expf(d); g_F2[idx] = __expf(LALPHA * d);
    }
}

// ---------------- K4: fused attention, JT=64, double-buffered, f32x2 ----------------
struct SmemAttn {
    float      Ps[2][JT][PAD];   // 67584 B
    float      Vs[2][JT][FO];    // 32768 B
    float      dD[2][JT], dF1[2][JT], dF2[2][JT];   // 1536 B
    unsigned   wB[2][256];       // [i*2+half], 2048 B
    float      sS[128], sE1[128], sE2[128];         // 1536 B
    float      Zs[128];          // 512 B
};
#define SMEM_ATTN sizeof(SmemAttn)

__global__ __launch_bounds__(256, 2) void k_attn(float* __restrict__ out) {
    extern __shared__ char smraw[];
    SmemAttn* sm = (SmemAttn*)smraw;
    const int h  = blockIdx.y;
    const int i0 = blockIdx.x * 128;
    const int tid  = threadIdx.x;
    const int tx   = tid & 15;    // phase-2 feature group
    const int ty   = tid >> 4;    // phase-2 row group (8 rows)
    const int lane = tid & 31;    // phase-1 j within tile (handles lane and lane+32)
    const int wrp  = tid >> 5;    // phase-1 row block (16 rows)

    if (tid < 128) {
        int idx = h*NN + i0 + tid;
        sm->sS[tid] = g_s[idx]; sm->sE1[tid] = g_E1[idx]; sm->sE2[tid] = g_E2[idx];
    }

    u64 acc[4][4] = {};
    u64 zp[8] = {};
    const unsigned mybit = 1u << lane;

    // tile loader: V (Wh rows), d-terms, mask words -> buffer b
    auto load_tile = [&](int jt, int b) {
        const int j0 = jt * JT;
        int f4 = tid & 15, j = tid >> 4;
        #pragma unroll
        for (int rep = 0; rep < 4; rep++) {
            int jj = j + rep * 16;
            *(float4*)&sm->Vs[b][jj][f4*4] =
                *(const float4*)&g_Wh[((size_t)h*NN + j0 + jj)*FO + f4*4];
        }
        if (tid < JT) {
            int idx = h*NN + j0 + tid;
            sm->dD[b][tid] = g_dd[idx]; sm->dF1[b][tid] = g_F1[idx]; sm->dF2[b][tid] = g_F2[idx];
        }
        // 128 rows x 2 mask words per 64-wide tile
        sm->wB[b][tid] = g_bits[(size_t)(i0 + (tid >> 1)) * NW + jt * 2 + (tid & 1)];
    };

    load_tile(0, 0);
    __syncthreads();

    for (int jt = 0; jt < NT; jt++) {
        const int b = jt & 1;

        // ---- phase 1: P weights for j=lane and j=lane+32 (STS.128 quads) ----
        {
            float dj0 = sm->dD[b][lane],    f10 = sm->dF1[b][lane],    f20 = sm->dF2[b][lane];
            float dj1 = sm->dD[b][lane+32], f11 = sm->dF1[b][lane+32], f21 = sm->dF2[b][lane+32];
            #pragma unroll
            for (int q = 0; q < 4; q++) {
                float4 wv0, wv1;
                float* wp0 = &wv0.x;
                float* wp1 = &wv1.x;
                #pragma unroll
                for (int r = 0; r < 4; r++) {
                    int i = wrp*16 + q*4 + r;
                    float si = sm->sS[i], e1 = sm->sE1[i], e2 = sm->sE2[i];
                    unsigned m0 = sm->wB[b][2*i], m1 = sm->wB[b][2*i+1];
                    float t0 = si + dj0;
                    float v0 = (t0 >= 0.f) ? e1*f10 : e2*f20;
                    wp0[r] = (m0 & mybit) ? v0 : 0.f;
                    float t1 = si + dj1;
                    float v1 = (t1 >= 0.f) ? e1*f11 : e2*f21;
                    wp1[r] = (m1 & mybit) ? v1 : 0.f;
                }
                *(float4*)&sm->Ps[b][lane   ][wrp*16 + q*4] = wv0;
                *(float4*)&sm->Ps[b][lane+32][wrp*16 + q*4] = wv1;
                add2(zp[2*q],   pk2(wv0.x, wv0.y));
                add2(zp[2*q+1], pk2(wv0.z, wv0.w));
                add2(zp[2*q],   pk2(wv1.x, wv1.y));
                add2(zp[2*q+1], pk2(wv1.z, wv1.w));
            }
        }
        // prefetch next tile into the other buffer (hides under phase 2)
        if (jt + 1 < NT) load_tile(jt + 1, b ^ 1);
        __syncthreads();

        // ---- phase 2: acc += P^T @ V  (LDS.128 quads, FFMA2) ----
        #pragma unroll
        for (int k = 0; k < JT; k++) {
            float4 pa = *(const float4*)&sm->Ps[b][k][ty*8];
            float4 pb = *(const float4*)&sm->Ps[b][k][ty*8 + 4];
            u64 p[4] = { pk2(pa.x, pa.y), pk2(pa.z, pa.w),
                         pk2(pb.x, pb.y), pk2(pb.z, pb.w) };
            float4 vv = *(const float4*)&sm->Vs[b][k][tx*4];
            u64 v0 = pk2(vv.x, vv.x), v1 = pk2(vv.y, vv.y);
            u64 v2 = pk2(vv.z, vv.z), v3 = pk2(vv.w, vv.w);
            #pragma unroll
            for (int ip = 0; ip < 4; ip++) {
                fma2(acc[ip][0], p[ip], v0); fma2(acc[ip][1], p[ip], v1);
                fma2(acc[ip][2], p[ip], v2); fma2(acc[ip][3], p[ip], v3);
            }
        }
        __syncthreads();   // buffer b reusable at jt+2
    }

    // ---- packed row-sum cross-lane reduction ----
    #pragma unroll
    for (int q = 0; q < 8; q++) {
        u64 v = zp[q];
        #pragma unroll
        for (int off = 16; off; off >>= 1)
            add2(v, __shfl_xor_sync(0xffffffffu, v, off));
        zp[q] = v;
    }
    if (lane == 0) {
        #pragma unroll
        for (int q = 0; q < 8; q++) {
            float a, b2; upk2(a, b2, zp[q]);
            sm->Zs[wrp*16 + 2*q] = a; sm->Zs[wrp*16 + 2*q + 1] = b2;
        }
    }
    __syncthreads();

    // ---- normalize + ELU + store [N, H*FO] ----
    #pragma unroll
    for (int ip = 0; ip < 4; ip++) {
        int il = ty*8 + 2*ip;
        float zi0 = 1.f / sm->Zs[il], zi1 = 1.f / sm->Zs[il + 1];
        float lo[4], hi[4];
        #pragma unroll
        for (int f = 0; f < 4; f++) upk2(lo[f], hi[f], acc[ip][f]);
        float4 o0, o1;
        o0.x = lo[0]*zi0; o0.y = lo[1]*zi0; o0.z = lo[2]*zi0; o0.w = lo[3]*zi0;
        o1.x = hi[0]*zi1; o1.y = hi[1]*zi1; o1.z = hi[2]*zi1; o1.w = hi[3]*zi1;
        o0.x = (o0.x > 0.f) ? o0.x : expm1f(o0.x);
        o0.y = (o0.y > 0.f) ? o0.y : expm1f(o0.y);
        o0.z = (o0.z > 0.f) ? o0.z : expm1f(o0.z);
        o0.w = (o0.w > 0.f) ? o0.w : expm1f(o0.w);
        o1.x = (o1.x > 0.f) ? o1.x : expm1f(o1.x);
        o1.y = (o1.y > 0.f) ? o1.y : expm1f(o1.y);
        o1.z = (o1.z > 0.f) ? o1.z : expm1f(o1.z);
        o1.w = (o1.w > 0.f) ? o1.w : expm1f(o1.w);
        *(float4*)&out[(size_t)(i0 + il    ) * (HH*FO) + h*FO + tx*4] = o0;
        *(float4*)&out[(size_t)(i0 + il + 1) * (HH*FO) + h*FO + tx*4] = o1;
    }
}

// ---------------- launcher ----------------
extern "C" void kernel_launch(void* const* d_in, const int* in_sizes, int n_in,
                              void* d_out, int out_size) {
    const float* X     = (const float*)d_in[0];
    const int*   adj   = (const int*)  d_in[1];
    const float* W     = (const float*)d_in[2];
    const float* a_src = (const float*)d_in[3];
    const float* a_dst = (const float*)d_in[4];
    float* out = (float*)d_out;

    cudaFuncSetAttribute(k_attn, cudaFuncAttributeMaxDynamicSharedMemorySize, SMEM_ATTN);

    k_bitpack<<<(NN * NW) / 8, 256>>>(adj);
    k_wh     <<<dim3(NN/128, HH), 256>>>(X, W);
    k_nodes  <<<(HH * NN) / 8, 256>>>(a_src, a_dst);
    k_attn   <<<dim3(NN/128, HH), 256, SMEM_ATTN>>>(out);
}

// round 11
// speedup vs baseline: 1.8832x; 1.4489x over previous
#include <cuda_runtime.h>
#include <cuda_bf16.h>
#include <cstdint>

#define NN   4096
#define FIN  512
#define HH   8
#define FO   64
#define LALPHA 0.2f
#define NW   128        // mask words per row
#define JTT  64         // j per tile
#define NJT  (NN/JTT)   // 64 tiles
#define NTF  9          // n-tiles of 8 (64 feats + Z col + pad)
#define GT_U4 2304      // uint4 per (h,jt) G tile block = 36864 B
#define PAD  132

typedef unsigned long long u64;

// ---------------- f32x2 helpers (k_wh) ----------------
__device__ __forceinline__ u64 pk2(float lo, float hi) {
    u64 r; asm("mov.b64 %0, {%1,%2};" : "=l"(r) : "f"(lo), "f"(hi)); return r;
}
__device__ __forceinline__ void fma2(u64 &d, u64 a, u64 b) {
    asm("fma.rn.f32x2 %0, %1, %2, %3;" : "=l"(d) : "l"(a), "l"(b), "l"(d));
}
__device__ __forceinline__ void upk2(float &lo, float &hi, u64 v) {
    asm("mov.b64 {%0,%1}, %2;" : "=f"(lo), "=f"(hi) : "l"(v));
}

// ---------------- mma / cp.async helpers (arch-neutral PTX) ----------------
__device__ __forceinline__ uint32_t smem_u32(const void* p) {
    uint32_t a;
    asm("{ .reg .u64 t; cvta.to.shared.u64 t, %1; cvt.u32.u64 %0, t; }" : "=r"(a) : "l"(p));
    return a;
}
__device__ __forceinline__ void mma16816(float* c, const uint32_t* a, uint32_t b0, uint32_t b1) {
    asm volatile("mma.sync.aligned.m16n8k16.row.col.f32.bf16.bf16.f32 "
        "{%0,%1,%2,%3}, {%4,%5,%6,%7}, {%8,%9}, {%0,%1,%2,%3};"
        : "+f"(c[0]), "+f"(c[1]), "+f"(c[2]), "+f"(c[3])
        : "r"(a[0]), "r"(a[1]), "r"(a[2]), "r"(a[3]), "r"(b0), "r"(b1));
}
__device__ __forceinline__ void cpa16(uint32_t d, const void* s) {
    asm volatile("cp.async.cg.shared.global [%0], [%1], 16;" :: "r"(d), "l"(s));
}
__device__ __forceinline__ void cpa4(uint32_t d, const void* s) {
    asm volatile("cp.async.ca.shared.global [%0], [%1], 4;" :: "r"(d), "l"(s));
}
#define CP_COMMIT() asm volatile("cp.async.commit_group;" ::: "memory")
#define CP_WAIT0()  asm volatile("cp.async.wait_group 0;" ::: "memory")

// ---------------- scratch ----------------
__device__ float    g_Wh[(size_t)HH*NN*FO];
__device__ unsigned g_bits[(size_t)NN*NW];
__device__ float    g_s [HH*NN], g_E1[HH*NN], g_E2[HH*NN];
__device__ float    g_dd[HH*NN], g_F1[HH*NN], g_F2[HH*NN];
__device__ uint4    g_G[(size_t)HH*NJT*GT_U4];   // pre-fragmented split-bf16 G, 18.9 MB

// ---------------- K1: bit-pack adjacency ----------------
__global__ void k_bitpack(const int* __restrict__ adj) {
    int t = blockIdx.x * blockDim.x + threadIdx.x;
    int w = t >> 5, lane = t & 31;
    int v = adj[(size_t)w * 32 + lane];
    unsigned b = __ballot_sync(0xffffffffu, v > 0);
    if (lane == 0) g_bits[w] = b;
}

// ---------------- K2: Wh[h] = X @ W[h] (f32x2, from R10) ----------------
__global__ __launch_bounds__(256, 2) void k_wh(const float* __restrict__ X,
                                               const float* __restrict__ W) {
    __shared__ float As[32][PAD];
    __shared__ float Bs[32][64];
    const int h = blockIdx.y, i0 = blockIdx.x * 128, tid = threadIdx.x;
    const int tx = tid & 15, ty = tid >> 4;
    const float* Wb = W + (size_t)h * FIN * FO;
    u64 acc[4][4] = {};
    for (int kt = 0; kt < FIN; kt += 32) {
        __syncthreads();
        {
            int k4 = tid & 7, il = tid >> 3;
            #pragma unroll
            for (int rep = 0; rep < 4; rep++) {
                int i = il + rep * 32;
                float4 f = *(const float4*)&X[(size_t)(i0 + i) * FIN + kt + k4 * 4];
                As[k4*4+0][i] = f.x; As[k4*4+1][i] = f.y;
                As[k4*4+2][i] = f.z; As[k4*4+3][i] = f.w;
            }
        }
        {
            int f4 = tid & 15, k = tid >> 4;
            #pragma unroll
            for (int rep = 0; rep < 2; rep++) {
                int kk = k + rep * 16;
                *(float4*)&Bs[kk][f4*4] = *(const float4*)&Wb[(size_t)(kt+kk)*FO + f4*4];
            }
        }
        __syncthreads();
        #pragma unroll
        for (int k = 0; k < 32; k++) {
            float4 pa = *(const float4*)&As[k][ty*8];
            float4 pb = *(const float4*)&As[k][ty*8 + 4];
            u64 p[4] = { pk2(pa.x, pa.y), pk2(pa.z, pa.w),
                         pk2(pb.x, pb.y), pk2(pb.z, pb.w) };
            float4 vv = *(const float4*)&Bs[k][tx*4];
            u64 v0 = pk2(vv.x, vv.x), v1 = pk2(vv.y, vv.y);
            u64 v2 = pk2(vv.z, vv.z), v3 = pk2(vv.w, vv.w);
            #pragma unroll
            for (int ip = 0; ip < 4; ip++) {
                fma2(acc[ip][0], p[ip], v0); fma2(acc[ip][1], p[ip], v1);
                fma2(acc[ip][2], p[ip], v2); fma2(acc[ip][3], p[ip], v3);
            }
        }
    }
    #pragma unroll
    for (int ip = 0; ip < 4; ip++) {
        float lo[4], hi[4];
        #pragma unroll
        for (int f = 0; f < 4; f++) upk2(lo[f], hi[f], acc[ip][f]);
        int i = i0 + ty*8 + 2*ip;
        float4 o0 = {lo[0], lo[1], lo[2], lo[3]};
        float4 o1 = {hi[0], hi[1], hi[2], hi[3]};
        *(float4*)&g_Wh[((size_t)h*NN + i    )*FO + tx*4] = o0;
        *(float4*)&g_Wh[((size_t)h*NN + i + 1)*FO + tx*4] = o1;
    }
}

// ---------------- K3: per-(h,n) s,d + exp factors ----------------
__global__ void k_nodes(const float* __restrict__ a_src,
                        const float* __restrict__ a_dst) {
    int gw = blockIdx.x * (blockDim.x >> 5) + (threadIdx.x >> 5);
    int lane = threadIdx.x & 31;
    int h = gw >> 12, n = gw & (NN - 1);
    const float* wr = g_Wh + ((size_t)h * NN + n) * FO;
    float w0 = wr[lane], w1 = wr[lane + 32];
    float s = w0 * a_src[h*FO + lane] + w1 * a_src[h*FO + lane + 32];
    float d = w0 * a_dst[h*FO + lane] + w1 * a_dst[h*FO + lane + 32];
    #pragma unroll
    for (int off = 16; off; off >>= 1) {
        s += __shfl_xor_sync(0xffffffffu, s, off);
        d += __shfl_xor_sync(0xffffffffu, d, off);
    }
    if (lane == 0) {
        int idx = h * NN + n;
        g_s [idx] = s; g_E1[idx] = __expf(s); g_E2[idx] = __expf(LALPHA * s);
        g_dd[idx] = d; g_F1[idx] = __expf(d); g_F2[idx] = __expf(LALPHA * d);
    }
}

// ---------------- K4: build G tiles, pre-laid in mma B-fragment order ----------------
// B frag (m16n8k16, col-major k x n): lane (g = lane>>2, t = lane&3):
//   b0 = { B[2t][g], B[2t+1][g] },  b1 = { B[2t+8][g], B[2t+9][g] }   (k, n=g)
// Stored per (kk, nt, pair): 32 lanes x uint4 {hi_b0, hi_b1, lo_b0, lo_b1}.
__global__ __launch_bounds__(256) void k_gtiles() {
    const int jt = blockIdx.x, h = blockIdx.y;
    const int tid = threadIdx.x, w = tid >> 5, lane = tid & 31;
    const int g = lane >> 2, t = lane & 3;
    uint4* base = g_G + (size_t)(h*NJT + jt) * GT_U4;
    for (int u = w; u < 72; u += 8) {
        int kk = u / 18, rem = u % 18, nt = rem >> 1, pair = rem & 1;
        int f = nt * 8 + g;
        int j0 = jt * JTT + kk * 16;
        const float* Fv = pair ? g_F2 : g_F1;
        int js[4] = { j0 + 2*t, j0 + 2*t + 1, j0 + 2*t + 8, j0 + 2*t + 9 };
        float v[4];
        #pragma unroll
        for (int m = 0; m < 4; m++) {
            float wv = (f < FO) ? g_Wh[((size_t)h*NN + js[m])*FO + f]
                                : ((f == FO) ? 1.0f : 0.0f);
            v[m] = wv * Fv[h*NN + js[m]];
        }
        unsigned hi[4], lo[4];
        #pragma unroll
        for (int m = 0; m < 4; m++) {
            __nv_bfloat16 hb = __float2bfloat16(v[m]);
            float r = v[m] - __bfloat162float(hb);
            __nv_bfloat16 lb = __float2bfloat16(r);
            hi[m] = __bfloat16_as_ushort(hb);
            lo[m] = __bfloat16_as_ushort(lb);
        }
        uint4 o;
        o.x = hi[0] | (hi[1] << 16);   // hi b0  (k=2t, 2t+1)
        o.y = hi[2] | (hi[3] << 16);   // hi b1  (k=2t+8, 2t+9)
        o.z = lo[0] | (lo[1] << 16);   // lo b0
        o.w = lo[2] | (lo[3] << 16);   // lo b1
        base[(size_t)((kk*NTF + nt)*2 + pair)*32 + lane] = o;
    }
}

// ---------------- K5: mma.sync fused attention ----------------
struct SmemMma {
    uint4    G[2][GT_U4];    // 73728 B
    float    dD[2][JTT];     // 512 B
    unsigned wB[2][256];     // 2048 B
};
#define SMEM_MMA sizeof(SmemMma)

__global__ __launch_bounds__(256, 2) void k_attn(float* __restrict__ out) {
    extern __shared__ char smraw[];
    SmemMma* sm = (SmemMma*)smraw;
    const int h  = blockIdx.y;
    const int i0 = blockIdx.x * 128;
    const int tid = threadIdx.x, w = tid >> 5, lane = tid & 31;
    const int g = lane >> 2, t = lane & 3;

    float acc1[NTF][4] = {};   // A1 @ (G1hi + G1lo)
    float acc2[NTF][4] = {};   // A2 @ (G2hi + G2lo)
    const int ia_l = w*16 + g, ib_l = ia_l + 8;
    const float sa  = g_s[h*NN + i0 + ia_l];
    const float sbv = g_s[h*NN + i0 + ib_l];

    auto load_tile = [&](int jt, int b) {
        const uint4* src = g_G + (size_t)(h*NJT + jt) * GT_U4;
        uint32_t dst = smem_u32(&sm->G[b][0]);
        #pragma unroll
        for (int r = 0; r < 9; r++)
            cpa16(dst + (uint32_t)(tid + r*256) * 16, src + tid + r*256);
        if (tid < JTT)
            cpa4(smem_u32(&sm->dD[b][tid]), &g_dd[h*NN + jt*JTT + tid]);
        cpa4(smem_u32(&sm->wB[b][tid]),
             &g_bits[(size_t)(i0 + (tid >> 1)) * NW + jt*2 + (tid & 1)]);
    };

    load_tile(0, 0); CP_COMMIT(); CP_WAIT0();
    __syncthreads();

    for (int jt = 0; jt < NJT; jt++) {
        const int b = jt & 1;
        if (jt + 1 < NJT) load_tile(jt + 1, b ^ 1);
        CP_COMMIT();

        const unsigned wa0 = sm->wB[b][2*ia_l], wa1 = sm->wB[b][2*ia_l + 1];
        const unsigned wb0 = sm->wB[b][2*ib_l], wb1 = sm->wB[b][2*ib_l + 1];
        const uint4* Gb = sm->G[b];

        #pragma unroll
        for (int kk = 0; kk < 4; kk++) {
            const unsigned wa = (kk < 2) ? wa0 : wa1;
            const unsigned wb = (kk < 2) ? wb0 : wb1;
            const int bb = (kk & 1) * 16 + 2*t;
            float2 dlo = *(const float2*)&sm->dD[b][kk*16 + 2*t];
            float2 dhi = *(const float2*)&sm->dD[b][kk*16 + 2*t + 8];
            bool e0 = (wa >> bb) & 1,       e1 = (wa >> (bb+1)) & 1;
            bool e2 = (wa >> (bb+8)) & 1,   e3 = (wa >> (bb+9)) & 1;
            bool q0 = (wb >> bb) & 1,       q1 = (wb >> (bb+1)) & 1;
            bool q2 = (wb >> (bb+8)) & 1,   q3 = (wb >> (bb+9)) & 1;
            float ta0 = sa  + dlo.x, ta1 = sa  + dlo.y, ta2 = sa  + dhi.x, ta3 = sa  + dhi.y;
            float tb0 = sbv + dlo.x, tb1 = sbv + dlo.y, tb2 = sbv + dhi.x, tb3 = sbv + dhi.y;
            uint32_t a1f[4], a2f[4];
            a1f[0] = (e0 && ta0 >= 0.f ? 0x3F80u : 0u) | (e1 && ta1 >= 0.f ? 0x3F800000u : 0u);
            a2f[0] = (e0 && ta0 <  0.f ? 0x3F80u : 0u) | (e1 && ta1 <  0.f ? 0x3F800000u : 0u);
            a1f[1] = (q0 && tb0 >= 0.f ? 0x3F80u : 0u) | (q1 && tb1 >= 0.f ? 0x3F800000u : 0u);
            a2f[1] = (q0 && tb0 <  0.f ? 0x3F80u : 0u) | (q1 && tb1 <  0.f ? 0x3F800000u : 0u);
            a1f[2] = (e2 && ta2 >= 0.f ? 0x3F80u : 0u) | (e3 && ta3 >= 0.f ? 0x3F800000u : 0u);
            a2f[2] = (e2 && ta2 <  0.f ? 0x3F80u : 0u) | (e3 && ta3 <  0.f ? 0x3F800000u : 0u);
            a1f[3] = (q2 && tb2 >= 0.f ? 0x3F80u : 0u) | (q3 && tb3 >= 0.f ? 0x3F800000u : 0u);
            a2f[3] = (q2 && tb2 <  0.f ? 0x3F80u : 0u) | (q3 && tb3 <  0.f ? 0x3F800000u : 0u);

            #pragma unroll
            for (int nt = 0; nt < NTF; nt++) {
                uint4 q1v = Gb[((kk*NTF + nt)*2 + 0)*32 + lane];
                mma16816(acc1[nt], a1f, q1v.x, q1v.y);   // A1 @ G1hi
                mma16816(acc1[nt], a1f, q1v.z, q1v.w);   // A1 @ G1lo
                uint4 q2v = Gb[((kk*NTF + nt)*2 + 1)*32 + lane];
                mma16816(acc2[nt], a2f, q2v.x, q2v.y);   // A2 @ G2hi
                mma16816(acc2[nt], a2f, q2v.z, q2v.w);   // A2 @ G2lo
            }
        }
        CP_WAIT0();
        __syncthreads();
    }

    // ---- epilogue: combine branches, normalize by Z (ones column), ELU, store ----
    const int ia = i0 + ia_l, ib = i0 + ib_l;
    const float E1a = g_E1[h*NN + ia], E2a = g_E2[h*NN + ia];
    const float E1b = g_E1[h*NN + ib], E2b = g_E2[h*NN + ib];
    const int src = lane & ~3;           // t=0 thread of this group holds col 64 (Z)
    float z1a = __shfl_sync(0xffffffffu, acc1[8][0], src);
    float z1b = __shfl_sync(0xffffffffu, acc1[8][2], src);
    float z2a = __shfl_sync(0xffffffffu, acc2[8][0], src);
    float z2b = __shfl_sync(0xffffffffu, acc2[8][2], src);
    const float inva = 1.f / (E1a*z1a + E2a*z2a);
    const float invb = 1.f / (E1b*z1b + E2b*z2b);
    #pragma unroll
    for (int nt = 0; nt < 8; nt++) {
        float oa0 = (E1a*acc1[nt][0] + E2a*acc2[nt][0]) * inva;
        float oa1 = (E1a*acc1[nt][1] + E2a*acc2[nt][1]) * inva;
        float ob0 = (E1b*acc1[nt][2] + E2b*acc2[nt][2]) * invb;
        float ob1 = (E1b*acc1[nt][3] + E2b*acc2[nt][3]) * invb;
        oa0 = (oa0 > 0.f) ? oa0 : expm1f(oa0);
        oa1 = (oa1 > 0.f) ? oa1 : expm1f(oa1);
        ob0 = (ob0 > 0.f) ? ob0 : expm1f(ob0);
        ob1 = (ob1 > 0.f) ? ob1 : expm1f(ob1);
        float2 fa = {oa0, oa1}, fb = {ob0, ob1};
        *(float2*)&out[(size_t)ia * (HH*FO) + h*FO + nt*8 + 2*t] = fa;
        *(float2*)&out[(size_t)ib * (HH*FO) + h*FO + nt*8 + 2*t] = fb;
    }
}

// ---------------- launcher ----------------
extern "C" void kernel_launch(void* const* d_in, const int* in_sizes, int n_in,
                              void* d_out, int out_size) {
    const float* X     = (const float*)d_in[0];
    const int*   adj   = (const int*)  d_in[1];
    const float* W     = (const float*)d_in[2];
    const float* a_src = (const float*)d_in[3];
    const float* a_dst = (const float*)d_in[4];
    float* out = (float*)d_out;

    cudaFuncSetAttribute(k_attn, cudaFuncAttributeMaxDynamicSharedMemorySize, SMEM_MMA);

    k_bitpack<<<(NN * NW) / 8, 256>>>(adj);
    k_wh     <<<dim3(NN/128, HH), 256>>>(X, W);
    k_nodes  <<<(HH * NN) / 8, 256>>>(a_src, a_dst);
    k_gtiles <<<dim3(NJT, HH), 256>>>();
    k_attn   <<<dim3(NN/128, HH), 256, SMEM_MMA>>>(out);
}

// round 13
// speedup vs baseline: 1.9502x; 1.0356x over previous
#include <cuda_runtime.h>
#include <cuda_bf16.h>
#include <cstdint>

#define NN   4096
#define FIN  512
#define HH   8
#define FO   64
#define LALPHA 0.2f
#define NW   128        // mask words per row
#define JTT  64         // j per tile
#define NJT  (NN/JTT)   // 64 tiles
#define NTF  9          // n-tiles of 8 (64 feats + Z col + pad)
#define GT_U4 2304      // uint4 per (h,jt) G tile block = 36864 B
#define ROWS 256        // i-rows per CTA (32 per warp, 2 row-fragments)
#define PAD  132

typedef unsigned long long u64;

// ---------------- f32x2 helpers (k_wh) ----------------
__device__ __forceinline__ u64 pk2(float lo, float hi) {
    u64 r; asm("mov.b64 %0, {%1,%2};" : "=l"(r) : "f"(lo), "f"(hi)); return r;
}
__device__ __forceinline__ void fma2(u64 &d, u64 a, u64 b) {
    asm("fma.rn.f32x2 %0, %1, %2, %3;" : "=l"(d) : "l"(a), "l"(b), "l"(d));
}
__device__ __forceinline__ void upk2(float &lo, float &hi, u64 v) {
    asm("mov.b64 {%0,%1}, %2;" : "=f"(lo), "=f"(hi) : "l"(v));
}

// ---------------- mma / cp.async helpers (arch-neutral PTX) ----------------
__device__ __forceinline__ uint32_t smem_u32(const void* p) {
    uint32_t a;
    asm("{ .reg .u64 t; cvta.to.shared.u64 t, %1; cvt.u32.u64 %0, t; }" : "=r"(a) : "l"(p));
    return a;
}
__device__ __forceinline__ void mma16816(float* c, const uint32_t* a, uint32_t b0, uint32_t b1) {
    asm volatile("mma.sync.aligned.m16n8k16.row.col.f32.bf16.bf16.f32 "
        "{%0,%1,%2,%3}, {%4,%5,%6,%7}, {%8,%9}, {%0,%1,%2,%3};"
        : "+f"(c[0]), "+f"(c[1]), "+f"(c[2]), "+f"(c[3])
        : "r"(a[0]), "r"(a[1]), "r"(a[2]), "r"(a[3]), "r"(b0), "r"(b1));
}
__device__ __forceinline__ void cpa16(uint32_t d, const void* s) {
    asm volatile("cp.async.cg.shared.global [%0], [%1], 16;" :: "r"(d), "l"(s));
}
__device__ __forceinline__ void cpa4(uint32_t d, const void* s) {
    asm volatile("cp.async.ca.shared.global [%0], [%1], 4;" :: "r"(d), "l"(s));
}
#define CP_COMMIT() asm volatile("cp.async.commit_group;" ::: "memory")
#define CP_WAIT0()  asm volatile("cp.async.wait_group 0;" ::: "memory")

// ---------------- scratch ----------------
__device__ float    g_Wh[(size_t)HH*NN*FO];
__device__ unsigned g_bits[(size_t)NN*NW];
__device__ float    g_s [HH*NN], g_E1[HH*NN], g_E2[HH*NN];
__device__ float    g_dd[HH*NN], g_F1[HH*NN], g_F2[HH*NN];
__device__ uint4    g_G[(size_t)HH*NJT*GT_U4];   // pre-fragmented split-bf16 G, 18.9 MB

// ---------------- K1: bit-pack adjacency ----------------
__global__ void k_bitpack(const int* __restrict__ adj) {
    int t = blockIdx.x * blockDim.x + threadIdx.x;
    int w = t >> 5, lane = t & 31;
    int v = adj[(size_t)w * 32 + lane];
    unsigned b = __ballot_sync(0xffffffffu, v > 0);
    if (lane == 0) g_bits[w] = b;
}

// ---------------- K2: Wh[h] = X @ W[h] (f32x2) ----------------
__global__ __launch_bounds__(256, 2) void k_wh(const float* __restrict__ X,
                                               const float* __restrict__ W) {
    __shared__ float As[32][PAD];
    __shared__ float Bs[32][64];
    const int h = blockIdx.y, i0 = blockIdx.x * 128, tid = threadIdx.x;
    const int tx = tid & 15, ty = tid >> 4;
    const float* Wb = W + (size_t)h * FIN * FO;
    u64 acc[4][4] = {};
    for (int kt = 0; kt < FIN; kt += 32) {
        __syncthreads();
        {
            int k4 = tid & 7, il = tid >> 3;
            #pragma unroll
            for (int rep = 0; rep < 4; rep++) {
                int i = il + rep * 32;
                float4 f = *(const float4*)&X[(size_t)(i0 + i) * FIN + kt + k4 * 4];
                As[k4*4+0][i] = f.x; As[k4*4+1][i] = f.y;
                As[k4*4+2][i] = f.z; As[k4*4+3][i] = f.w;
            }
        }
        {
            int f4 = tid & 15, k = tid >> 4;
            #pragma unroll
            for (int rep = 0; rep < 2; rep++) {
                int kk = k + rep * 16;
                *(float4*)&Bs[kk][f4*4] = *(const float4*)&Wb[(size_t)(kt+kk)*FO + f4*4];
            }
        }
        __syncthreads();
        #pragma unroll
        for (int k = 0; k < 32; k++) {
            float4 pa = *(const float4*)&As[k][ty*8];
            float4 pb = *(const float4*)&As[k][ty*8 + 4];
            u64 p[4] = { pk2(pa.x, pa.y), pk2(pa.z, pa.w),
                         pk2(pb.x, pb.y), pk2(pb.z, pb.w) };
            float4 vv = *(const float4*)&Bs[k][tx*4];
            u64 v0 = pk2(vv.x, vv.x), v1 = pk2(vv.y, vv.y);
            u64 v2 = pk2(vv.z, vv.z), v3 = pk2(vv.w, vv.w);
            #pragma unroll
            for (int ip = 0; ip < 4; ip++) {
                fma2(acc[ip][0], p[ip], v0); fma2(acc[ip][1], p[ip], v1);
                fma2(acc[ip][2], p[ip], v2); fma2(acc[ip][3], p[ip], v3);
            }
        }
    }
    #pragma unroll
    for (int ip = 0; ip < 4; ip++) {
        float lo[4], hi[4];
        #pragma unroll
        for (int f = 0; f < 4; f++) upk2(lo[f], hi[f], acc[ip][f]);
        int i = i0 + ty*8 + 2*ip;
        float4 o0 = {lo[0], lo[1], lo[2], lo[3]};
        float4 o1 = {hi[0], hi[1], hi[2], hi[3]};
        *(float4*)&g_Wh[((size_t)h*NN + i    )*FO + tx*4] = o0;
        *(float4*)&g_Wh[((size_t)h*NN + i + 1)*FO + tx*4] = o1;
    }
}

// ---------------- K3: per-(h,n) s,d + exp factors ----------------
__global__ void k_nodes(const float* __restrict__ a_src,
                        const float* __restrict__ a_dst) {
    int gw = blockIdx.x * (blockDim.x >> 5) + (threadIdx.x >> 5);
    int lane = threadIdx.x & 31;
    int h = gw >> 12, n = gw & (NN - 1);
    const float* wr = g_Wh + ((size_t)h * NN + n) * FO;
    float w0 = wr[lane], w1 = wr[lane + 32];
    float s = w0 * a_src[h*FO + lane] + w1 * a_src[h*FO + lane + 32];
    float d = w0 * a_dst[h*FO + lane] + w1 * a_dst[h*FO + lane + 32];
    #pragma unroll
    for (int off = 16; off; off >>= 1) {
        s += __shfl_xor_sync(0xffffffffu, s, off);
        d += __shfl_xor_sync(0xffffffffu, d, off);
    }
    if (lane == 0) {
        int idx = h * NN + n;
        g_s [idx] = s; g_E1[idx] = __expf(s); g_E2[idx] = __expf(LALPHA * s);
        g_dd[idx] = d; g_F1[idx] = __expf(d); g_F2[idx] = __expf(LALPHA * d);
    }
}

// ---------------- K4: build G tiles in mma B-fragment order ----------------
__global__ __launch_bounds__(256) void k_gtiles() {
    const int jt = blockIdx.x, h = blockIdx.y;
    const int tid = threadIdx.x, w = tid >> 5, lane = tid & 31;
    const int g = lane >> 2, t = lane & 3;
    uint4* base = g_G + (size_t)(h*NJT + jt) * GT_U4;
    for (int u = w; u < 72; u += 8) {
        int kk = u / 18, rem = u % 18, nt = rem >> 1, pair = rem & 1;
        int f = nt * 8 + g;
        int j0 = jt * JTT + kk * 16;
        const float* Fv = pair ? g_F2 : g_F1;
        int js[4] = { j0 + 2*t, j0 + 2*t + 1, j0 + 2*t + 8, j0 + 2*t + 9 };
        float v[4];
        #pragma unroll
        for (int m = 0; m < 4; m++) {
            float wv = (f < FO) ? g_Wh[((size_t)h*NN + js[m])*FO + f]
                                : ((f == FO) ? 1.0f : 0.0f);
            v[m] = wv * Fv[h*NN + js[m]];
        }
        unsigned hi[4], lo[4];
        #pragma unroll
        for (int m = 0; m < 4; m++) {
            __nv_bfloat16 hb = __float2bfloat16(v[m]);
            float r = v[m] - __bfloat162float(hb);
            __nv_bfloat16 lb = __float2bfloat16(r);
            hi[m] = __bfloat16_as_ushort(hb);
            lo[m] = __bfloat16_as_ushort(lb);
        }
        uint4 o;
        o.x = hi[0] | (hi[1] << 16);
        o.y = hi[2] | (hi[3] << 16);
        o.z = lo[0] | (lo[1] << 16);
        o.w = lo[2] | (lo[3] << 16);
        base[(size_t)((kk*NTF + nt)*2 + pair)*32 + lane] = o;
    }
}

// ---------------- K5: mma.sync fused attention, 256 rows/CTA ----------------
struct SmemMma {
    uint4    G[2][GT_U4];      // 73728 B
    float    dD[2][JTT];       // 512 B
    unsigned wB[2][2*ROWS];    // 4096 B
};
#define SMEM_MMA sizeof(SmemMma)

__global__ __launch_bounds__(256, 1) void k_attn(float* __restrict__ out) {
    extern __shared__ char smraw[];
    SmemMma* sm = (SmemMma*)smraw;
    const int h  = blockIdx.y;
    const int i0 = blockIdx.x * ROWS;
    const int tid = threadIdx.x, w = tid >> 5, lane = tid & 31;
    const int g = lane >> 2, t = lane & 3;

    // two row-fragments per warp: block A rows rA,rA+8; block B rows rB,rB+8
    const int rA = w*32 + g, rB = rA + 16;
    const float saA = g_s[h*NN + i0 + rA],      sbA = g_s[h*NN + i0 + rA + 8];
    const float saB = g_s[h*NN + i0 + rB],      sbB = g_s[h*NN + i0 + rB + 8];

    float acc1A[NTF][4] = {}, acc2A[NTF][4] = {};
    float acc1B[NTF][4] = {}, acc2B[NTF][4] = {};

    auto load_tile = [&](int jt, int b) {
        const uint4* src = g_G + (size_t)(h*NJT + jt) * GT_U4;
        uint32_t dst = smem_u32(&sm->G[b][0]);
        #pragma unroll
        for (int r = 0; r < 9; r++)
            cpa16(dst + (uint32_t)(tid + r*256) * 16, src + tid + r*256);
        if (tid < JTT)
            cpa4(smem_u32(&sm->dD[b][tid]), &g_dd[h*NN + jt*JTT + tid]);
        #pragma unroll
        for (int r = 0; r < 2; r++) {
            int idx = tid + r*256;   // 512 mask words (256 rows x 2)
            cpa4(smem_u32(&sm->wB[b][idx]),
                 &g_bits[(size_t)(i0 + (idx >> 1)) * NW + jt*2 + (idx & 1)]);
        }
    };

    load_tile(0, 0); CP_COMMIT(); CP_WAIT0();
    __syncthreads();

    for (int jt = 0; jt < NJT; jt++) {
        const int b = jt & 1;
        if (jt + 1 < NJT) load_tile(jt + 1, b ^ 1);
        CP_COMMIT();

        // mask words for this thread's 4 rows (2 words each: j<32, j>=32)
        const unsigned mA_a0 = sm->wB[b][2*rA],       mA_a1 = sm->wB[b][2*rA + 1];
        const unsigned mA_b0 = sm->wB[b][2*(rA+8)],   mA_b1 = sm->wB[b][2*(rA+8) + 1];
        const unsigned mB_a0 = sm->wB[b][2*rB],       mB_a1 = sm->wB[b][2*rB + 1];
        const unsigned mB_b0 = sm->wB[b][2*(rB+8)],   mB_b1 = sm->wB[b][2*(rB+8) + 1];
        const uint4* Gb = sm->G[b];

        #pragma unroll
        for (int kk = 0; kk < 4; kk++) {
            const int bb = (kk & 1) * 16 + 2*t;
            float2 dlo = *(const float2*)&sm->dD[b][kk*16 + 2*t];
            float2 dhi = *(const float2*)&sm->dD[b][kk*16 + 2*t + 8];

            uint32_t a1A[4], a2A[4], a1B[4], a2B[4];
            {   // block A
                const unsigned wa = (kk < 2) ? mA_a0 : mA_a1;
                const unsigned wb = (kk < 2) ? mA_b0 : mA_b1;
                bool e0=(wa>>bb)&1, e1=(wa>>(bb+1))&1, e2=(wa>>(bb+8))&1, e3=(wa>>(bb+9))&1;
                bool q0=(wb>>bb)&1, q1=(wb>>(bb+1))&1, q2=(wb>>(bb+8))&1, q3=(wb>>(bb+9))&1;
                float ta0=saA+dlo.x, ta1=saA+dlo.y, ta2=saA+dhi.x, ta3=saA+dhi.y;
                float tb0=sbA+dlo.x, tb1=sbA+dlo.y, tb2=sbA+dhi.x, tb3=sbA+dhi.y;
                a1A[0]=(e0&&ta0>=0.f?0x3F80u:0u)|(e1&&ta1>=0.f?0x3F800000u:0u);
                a2A[0]=(e0&&ta0< 0.f?0x3F80u:0u)|(e1&&ta1< 0.f?0x3F800000u:0u);
                a1A[1]=(q0&&tb0>=0.f?0x3F80u:0u)|(q1&&tb1>=0.f?0x3F800000u:0u);
                a2A[1]=(q0&&tb0< 0.f?0x3F80u:0u)|(q1&&tb1< 0.f?0x3F800000u:0u);
                a1A[2]=(e2&&ta2>=0.f?0x3F80u:0u)|(e3&&ta3>=0.f?0x3F800000u:0u);
                a2A[2]=(e2&&ta2< 0.f?0x3F80u:0u)|(e3&&ta3< 0.f?0x3F800000u:0u);
                a1A[3]=(q2&&tb2>=0.f?0x3F80u:0u)|(q3&&tb3>=0.f?0x3F800000u:0u);
                a2A[3]=(q2&&tb2< 0.f?0x3F80u:0u)|(q3&&tb3< 0.f?0x3F800000u:0u);
            }
            {   // block B
                const unsigned wa = (kk < 2) ? mB_a0 : mB_a1;
                const unsigned wb = (kk < 2) ? mB_b0 : mB_b1;
                bool e0=(wa>>bb)&1, e1=(wa>>(bb+1))&1, e2=(wa>>(bb+8))&1, e3=(wa>>(bb+9))&1;
                bool q0=(wb>>bb)&1, q1=(wb>>(bb+1))&1, q2=(wb>>(bb+8))&1, q3=(wb>>(bb+9))&1;
                float ta0=saB+dlo.x, ta1=saB+dlo.y, ta2=saB+dhi.x, ta3=saB+dhi.y;
                float tb0=sbB+dlo.x, tb1=sbB+dlo.y, tb2=sbB+dhi.x, tb3=sbB+dhi.y;
                a1B[0]=(e0&&ta0>=0.f?0x3F80u:0u)|(e1&&ta1>=0.f?0x3F800000u:0u);
                a2B[0]=(e0&&ta0< 0.f?0x3F80u:0u)|(e1&&ta1< 0.f?0x3F800000u:0u);
                a1B[1]=(q0&&tb0>=0.f?0x3F80u:0u)|(q1&&tb1>=0.f?0x3F800000u:0u);
                a2B[1]=(q0&&tb0< 0.f?0x3F80u:0u)|(q1&&tb1< 0.f?0x3F800000u:0u);
                a1B[2]=(e2&&ta2>=0.f?0x3F80u:0u)|(e3&&ta3>=0.f?0x3F800000u:0u);
                a2B[2]=(e2&&ta2< 0.f?0x3F80u:0u)|(e3&&ta3< 0.f?0x3F800000u:0u);
                a1B[3]=(q2&&tb2>=0.f?0x3F80u:0u)|(q3&&tb3>=0.f?0x3F800000u:0u);
                a2B[3]=(q2&&tb2< 0.f?0x3F80u:0u)|(q3&&tb3< 0.f?0x3F800000u:0u);
            }

            #pragma unroll
            for (int nt = 0; nt < NTF; nt++) {
                uint4 q1v = Gb[((kk*NTF + nt)*2 + 0)*32 + lane];  // G1 hi|lo
                uint4 q2v = Gb[((kk*NTF + nt)*2 + 1)*32 + lane];  // G2 hi|lo
                mma16816(acc1A[nt], a1A, q1v.x, q1v.y);
                mma16816(acc1A[nt], a1A, q1v.z, q1v.w);
                mma16816(acc2A[nt], a2A, q2v.x, q2v.y);
                mma16816(acc2A[nt], a2A, q2v.z, q2v.w);
                mma16816(acc1B[nt], a1B, q1v.x, q1v.y);
                mma16816(acc1B[nt], a1B, q1v.z, q1v.w);
                mma16816(acc2B[nt], a2B, q2v.x, q2v.y);
                mma16816(acc2B[nt], a2B, q2v.z, q2v.w);
            }
        }
        CP_WAIT0();
        __syncthreads();
    }

    // ---- epilogue: combine branches, normalize by Z (ones col), ELU, store ----
    const int src = lane & ~3;   // t=0 lane of the group holds col 64 (Z)
    #pragma unroll
    for (int blk = 0; blk < 2; blk++) {
        float (*A1)[4] = blk ? acc1B : acc1A;
        float (*A2)[4] = blk ? acc2B : acc2A;
        const int ia = i0 + (blk ? rB : rA), ib = ia + 8;
        const float E1a = g_E1[h*NN + ia], E2a = g_E2[h*NN + ia];
        const float E1b = g_E1[h*NN + ib], E2b = g_E2[h*NN + ib];
        float z1a = __shfl_sync(0xffffffffu, A1[8][0], src);
        float z1b = __shfl_sync(0xffffffffu, A1[8][2], src);
        float z2a = __shfl_sync(0xffffffffu, A2[8][0], src);
        float z2b = __shfl_sync(0xffffffffu, A2[8][2], src);
        const float inva = 1.f / (E1a*z1a + E2a*z2a);
        const float invb = 1.f / (E1b*z1b + E2b*z2b);
        #pragma unroll
        for (int nt = 0; nt < 8; nt++) {
            float oa0 = (E1a*A1[nt][0] + E2a*A2[nt][0]) * inva;
            float oa1 = (E1a*A1[nt][1] + E2a*A2[nt][1]) * inva;
            float ob0 = (E1b*A1[nt][2] + E2b*A2[nt][2]) * invb;
            float ob1 = (E1b*A1[nt][3] + E2b*A2[nt][3]) * invb;
            oa0 = (oa0 > 0.f) ? oa0 : expm1f(oa0);
            oa1 = (oa1 > 0.f) ? oa1 : expm1f(oa1);
            ob0 = (ob0 > 0.f) ? ob0 : expm1f(ob0);
            ob1 = (ob1 > 0.f) ? ob1 : expm1f(ob1);
            float2 fa = {oa0, oa1}, fb = {ob0, ob1};
            *(float2*)&out[(size_t)ia * (HH*FO) + h*FO + nt*8 + 2*t] = fa;
            *(float2*)&out[(size_t)ib * (HH*FO) + h*FO + nt*8 + 2*t] = fb;
        }
    }
}

// ---------------- launcher ----------------
extern "C" void kernel_launch(void* const* d_in, const int* in_sizes, int n_in,
                              void* d_out, int out_size) {
    const float* X     = (const float*)d_in[0];
    const int*   adj   = (const int*)  d_in[1];
    const float* W     = (const float*)d_in[2];
    const float* a_src = (const float*)d_in[3];
    const float* a_dst = (const float*)d_in[4];
    float* out = (float*)d_out;

    cudaFuncSetAttribute(k_attn, cudaFuncAttributeMaxDynamicSharedMemorySize, SMEM_MMA);

    k_bitpack<<<(NN * NW) / 8, 256>>>(adj);
    k_wh     <<<dim3(NN/128, HH), 256>>>(X, W);
    k_nodes  <<<(HH * NN) / 8, 256>>>(a_src, a_dst);
    k_gtiles <<<dim3(NJT, HH), 256>>>();
    k_attn   <<<dim3(NN/ROWS, HH), 256, SMEM_MMA>>>(out);
}